// round 12
// baseline (speedup 1.0000x reference)
#include <cuda_runtime.h>
#include <cuda_fp16.h>
#include <stdint.h>
#include <math.h>

// Problem constants
#define BN 64
#define SN 128
#define DN 128
#define VN 512
#define CN 256
#define NNM 256   // memory slots N
#define MN 64     // memory width M
#define NT 512    // threads per CTA

#define KG 448            // gates GEMV k (192 + 256)
#define KG8 (KG/8)        // 56
#define KH8 (CN/8)        // 32
#define KO 320            // out GEMV k (256 + 64)
#define KO4 (KO/4)        // 80
#define NHEAD 198

struct __align__(16) h8 { __half2 a, b, c, d; };   // 8 halves = 16B

// Weight panels (filled by prep kernel each launch)
__device__ h8     g_Wgh[KG8 * 1024];   // gates fp16: [g][permuted row]
__device__ h8     g_Whh[KH8 * NHEAD];  // heads fp16: [g][row]
__device__ float4 g_Wo[KO4 * VN];      // out fp32:   [kk][row]
__device__ float  g_gb[1024];          // b_ih + b_hh, permuted
__device__ float  g_hb[NHEAD];         // head biases
// Recurrent trace: [h(256)|rv(64)] per (b,s) for the deferred out-projection
__device__ float4 g_hrv[BN * SN * KO4];
// h-half exchange buffers: [(b*2+r)][buf(2)][128] and per-rank step flags
__device__ float  g_hx[BN * 2 * 2 * 128];
__device__ int    g_flag[BN * 2];

// ---------------- SMEM layout (float offsets) ----------------
#define MEM_OFF   0
#define MEM_STR   65
#define ACT_OFF   16640   // [emb(128)|rv(64)|h_prev(256)] = 448, pad 464
#define HB0_OFF   17104   // h|rv buffer 0: [h(256)|rv(64)]
#define HB1_OFF   17424   // h|rv buffer 1
#define C_OFF     17744   // c state, my 128 lanes
#define G_OFF     17872   // my 512 gate pre-activations
#define KEY_OFF   18384
#define ER_OFF    18448
#define AD_OFF    18512
#define RW_OFF    18576
#define WG_OFF    18832
#define WW_OFF    19088
#define RED_OFF   19344
#define SCAL_OFF  19364
#define XR_OFF    19372   // x row (128 ints)
#define SMEM_FLOATS 19504
// scal indices
#define SC_BETA 0
#define SC_GATE 1
#define SC_GAMMA 2
#define SC_SH0 3
#define SC_SH1 4
#define SC_SH2 5
#define SC_KN 6

__device__ __forceinline__ float sigf(float x) { return 1.0f / (1.0f + expf(-x)); }
__device__ __forceinline__ float softplusf(float x) {
    return fmaxf(x, 0.0f) + log1pf(expf(-fabsf(x)));
}

__device__ __forceinline__ float blockReduceSum(float v, float* red) {
    #pragma unroll
    for (int o = 16; o; o >>= 1) v += __shfl_down_sync(0xffffffffu, v, o);
    int wid = threadIdx.x >> 5, lane = threadIdx.x & 31;
    __syncthreads();
    if (lane == 0) red[wid] = v;
    __syncthreads();
    if (wid == 0) {
        v = (lane < (NT / 32)) ? red[lane] : 0.0f;
        #pragma unroll
        for (int o = 8; o; o >>= 1) v += __shfl_down_sync(0xffffffffu, v, o);
        if (lane == 0) red[0] = v;
    }
    __syncthreads();
    return red[0];
}

__device__ __forceinline__ float blockReduceMax(float v, float* red) {
    #pragma unroll
    for (int o = 16; o; o >>= 1) v = fmaxf(v, __shfl_down_sync(0xffffffffu, v, o));
    int wid = threadIdx.x >> 5, lane = threadIdx.x & 31;
    __syncthreads();
    if (lane == 0) red[wid] = v;
    __syncthreads();
    if (wid == 0) {
        v = (lane < (NT / 32)) ? red[lane] : -INFINITY;
        #pragma unroll
        for (int o = 8; o; o >>= 1) v = fmaxf(v, __shfl_down_sync(0xffffffffu, v, o));
        if (lane == 0) red[0] = v;
    }
    __syncthreads();
    return red[0];
}

// ================= prep: build weight panels =================
#define NP_WGH (KG8 * 1024)
#define NP_WHH (KH8 * NHEAD)
#define NP_WO  (KO4 * VN)
#define NP_GB  1024
#define NP_HB  NHEAD
#define NP_FLAG (BN * 2)
#define NP_TOTAL (NP_WGH + NP_WHH + NP_WO + NP_GB + NP_HB + NP_FLAG)

__device__ __forceinline__ h8 pack8(float4 lo, float4 hi) {
    h8 r;
    r.a = __floats2half2_rn(lo.x, lo.y);
    r.b = __floats2half2_rn(lo.z, lo.w);
    r.c = __floats2half2_rn(hi.x, hi.y);
    r.d = __floats2half2_rn(hi.z, hi.w);
    return r;
}

// Permuted gate row: prow = r*512 + q*128 + l <-> global row q*256 + r*128 + l
__device__ __forceinline__ int perm_to_global(int prow) {
    int r = (prow >> 9) & 1, q = (prow >> 7) & 3, l = prow & 127;
    return q * 256 + r * 128 + l;
}

__global__ void prep_kernel(
    const float* __restrict__ W_ih, const float* __restrict__ W_hh,
    const float* __restrict__ b_ih, const float* __restrict__ b_hh,
    const float* __restrict__ key_W, const float* __restrict__ key_b,
    const float* __restrict__ beta_W, const float* __restrict__ beta_b,
    const float* __restrict__ gate_W, const float* __restrict__ gate_b,
    const float* __restrict__ shift_W, const float* __restrict__ shift_b,
    const float* __restrict__ gamma_W, const float* __restrict__ gamma_b,
    const float* __restrict__ erase_W, const float* __restrict__ erase_b,
    const float* __restrict__ add_W, const float* __restrict__ add_b,
    const float* __restrict__ out_W)
{
    int idx = blockIdx.x * blockDim.x + threadIdx.x;
    if (idx < NP_WGH) {
        int g = idx >> 10, prow = idx & 1023;
        int j = perm_to_global(prow);
        int k = g * 8;
        float4 lo, hi;
        if (k < 192) {
            lo = *(const float4*)(W_ih + j * 192 + k);
            hi = *(const float4*)(W_ih + j * 192 + k + 4);
        } else {
            lo = *(const float4*)(W_hh + j * 256 + (k - 192));
            hi = *(const float4*)(W_hh + j * 256 + (k - 188));
        }
        g_Wgh[idx] = pack8(lo, hi);
        return;
    }
    idx -= NP_WGH;
    if (idx < NP_WHH) {
        int g = idx / NHEAD, j = idx % NHEAD;
        const float* wr;
        if (j < 64)        wr = key_W   + j * CN;
        else if (j == 64)  wr = beta_W;
        else if (j == 65)  wr = gate_W;
        else if (j < 69)   wr = shift_W + (j - 66) * CN;
        else if (j == 69)  wr = gamma_W;
        else if (j < 134)  wr = erase_W + (j - 70) * CN;
        else               wr = add_W   + (j - 134) * CN;
        int k = g * 8;
        float4 lo = *(const float4*)(wr + k);
        float4 hi = *(const float4*)(wr + k + 4);
        g_Whh[idx] = pack8(lo, hi);
        return;
    }
    idx -= NP_WHH;
    if (idx < NP_WO) {
        int kk = idx >> 9, j = idx & 511;
        g_Wo[idx] = *(const float4*)(out_W + j * KO + kk * 4);
        return;
    }
    idx -= NP_WO;
    if (idx < NP_GB) {
        int j = perm_to_global(idx);
        g_gb[idx] = b_ih[j] + b_hh[j];
        return;
    }
    idx -= NP_GB;
    if (idx < NP_HB) {
        int j = idx;
        float bias;
        if (j < 64)        bias = key_b[j];
        else if (j == 64)  bias = beta_b[0];
        else if (j == 65)  bias = gate_b[0];
        else if (j < 69)   bias = shift_b[j - 66];
        else if (j == 69)  bias = gamma_b[0];
        else if (j < 134)  bias = erase_b[j - 70];
        else               bias = add_b[j - 134];
        g_hb[j] = bias;
        return;
    }
    idx -= NP_HB;
    if (idx < NP_FLAG) g_flag[idx] = 0;   // reset handshake flags every launch
}

// ================= main persistent kernel: 2 CTAs per batch =================
// grid = 128 CTAs <= 148 SMs at 1 CTA/SM -> single wave, pairs co-resident.
extern __shared__ float sm[];

__global__ void __launch_bounds__(NT, 1) ntm_kernel(
    const int*   __restrict__ x,
    const float* __restrict__ emb,
    const float* __restrict__ mem_init)
{
    const int t = threadIdx.x;
    const int b = blockIdx.x >> 1;          // batch = pair id
    const int r = blockIdx.x & 1;           // rank within pair
    const int peer = r ^ 1;
    const int myid = (b << 1) | r;
    const int pid  = (b << 1) | peer;

    // ---- init state ----
    for (int i = t; i < NNM * MN; i += NT) {
        int n = i >> 6, m = i & 63;
        sm[MEM_OFF + n * MEM_STR + m] = mem_init[(b * NNM + n) * MN + m];
    }
    for (int i = t; i < 464; i += NT) sm[ACT_OFF + i] = 0.0f;
    for (int i = t; i < 640; i += NT) sm[HB0_OFF + i] = 0.0f;  // HB0+HB1 contiguous
    for (int i = t; i < 128; i += NT) sm[C_OFF + i] = 0.0f;
    for (int i = t; i < NNM; i += NT) sm[RW_OFF + i] = 0.0f;
    if (t < SN) ((int*)sm)[XR_OFF + t] = x[b * SN + t];
    __syncthreads();

    const float gbr = g_gb[(r << 9) + t];   // my permuted gate-row bias
    float hbr = 0.0f;
    if (t < NHEAD) hbr = g_hb[t];

    for (int s = 0; s < SN; s++) {
        const int pcur = s & 1;
        const int HBc = pcur ? HB1_OFF : HB0_OFF;
        const int HBp = pcur ? HB0_OFF : HB1_OFF;

        // ---- A: build ACT = [emb(128) | rv_prev(64) | h_prev(256)] ----
        if (t < MN) {
            sm[ACT_OFF + 128 + t] = sm[HBp + 256 + t];
        } else if (t < 64 + DN) {
            int tt = t - 64;
            int xi = ((int*)sm)[XR_OFF + s];
            sm[ACT_OFF + tt] = emb[xi * DN + tt];
        } else if (t >= 256) {
            sm[ACT_OFF + 192 + (t - 256)] = sm[HBp + (t - 256)];
        }
        __syncthreads();

        // ---- B: my 512 gate rows (fp16 weights, fp32 accum), 8 LDG.128 in flight ----
        {
            const float4* av4 = (const float4*)(sm + ACT_OFF);
            const h8* wp = &g_Wgh[(r << 9) + t];
            float4 a0 = make_float4(0.f, 0.f, 0.f, 0.f);
            #pragma unroll 1
            for (int kb = 0; kb < KG8; kb += 8) {
                h8 w[8];
                #pragma unroll
                for (int u = 0; u < 8; u++) w[u] = wp[(kb + u) * 1024];
                #pragma unroll
                for (int u = 0; u < 8; u++) {
                    float4 av0 = av4[(kb + u) * 2];
                    float4 av1 = av4[(kb + u) * 2 + 1];
                    float2 f;
                    f = __half22float2(w[u].a); a0.x = fmaf(f.x, av0.x, a0.x); a0.y = fmaf(f.y, av0.y, a0.y);
                    f = __half22float2(w[u].b); a0.z = fmaf(f.x, av0.z, a0.z); a0.w = fmaf(f.y, av0.w, a0.w);
                    f = __half22float2(w[u].c); a0.x = fmaf(f.x, av1.x, a0.x); a0.y = fmaf(f.y, av1.y, a0.y);
                    f = __half22float2(w[u].d); a0.z = fmaf(f.x, av1.z, a0.z); a0.w = fmaf(f.y, av1.w, a0.w);
                }
            }
            sm[G_OFF + t] = gbr + (a0.x + a0.y) + (a0.z + a0.w);
        }
        __syncthreads();

        // ---- C: LSTM pointwise for my 128 lanes; exchange h halves via L2 ----
        if (t < 128) {
            float ig = sm[G_OFF + t];
            float fg = sm[G_OFF + 128 + t];
            float gg = sm[G_OFF + 256 + t];
            float og = sm[G_OFF + 384 + t];
            float cc = sigf(fg) * sm[C_OFF + t] + sigf(ig) * tanhf(gg);
            sm[C_OFF + t] = cc;
            float hh = sigf(og) * tanhf(cc);
            sm[HBc + (r << 7) + t] = hh;                       // local half
            g_hx[(myid << 8) + (pcur << 7) + t] = hh;          // publish for peer
            __threadfence();                                   // data -> L2 before flag
        }
        __syncthreads();
        if (t == 0) {
            *(volatile int*)&g_flag[myid] = s + 1;             // release my step
            while (*(volatile int*)&g_flag[pid] < s + 1) { }   // acquire peer step
        }
        __syncthreads();
        if (t < 128) {
            sm[HBc + (peer << 7) + t] =
                __ldcg(&g_hx[(pid << 8) + (pcur << 7) + t]);   // L2 read, bypass L1
        }
        __syncthreads();

        // ---- D: head projections (198 rows x 256), replicated ----
        if (t < NHEAD) {
            const float4* h4 = (const float4*)(sm + HBc);
            float4 a = make_float4(0.f, 0.f, 0.f, 0.f);
            #pragma unroll 1
            for (int kb = 0; kb < KH8; kb += 4) {
                const h8* p = &g_Whh[kb * NHEAD + t];
                h8 w[4];
                #pragma unroll
                for (int u = 0; u < 4; u++) w[u] = p[u * NHEAD];
                #pragma unroll
                for (int u = 0; u < 4; u++) {
                    float4 hv0 = h4[(kb + u) * 2];
                    float4 hv1 = h4[(kb + u) * 2 + 1];
                    float2 f;
                    f = __half22float2(w[u].a); a.x = fmaf(f.x, hv0.x, a.x); a.y = fmaf(f.y, hv0.y, a.y);
                    f = __half22float2(w[u].b); a.z = fmaf(f.x, hv0.z, a.z); a.w = fmaf(f.y, hv0.w, a.w);
                    f = __half22float2(w[u].c); a.x = fmaf(f.x, hv1.x, a.x); a.y = fmaf(f.y, hv1.y, a.y);
                    f = __half22float2(w[u].d); a.z = fmaf(f.x, hv1.z, a.z); a.w = fmaf(f.y, hv1.w, a.w);
                }
            }
            float acc = hbr + (a.x + a.y) + (a.z + a.w);
            if (t < 64)        sm[KEY_OFF + t] = acc;
            else if (t == 64)  sm[SCAL_OFF + SC_BETA]  = softplusf(acc);
            else if (t == 65)  sm[SCAL_OFF + SC_GATE]  = sigf(acc);
            else if (t < 69)   sm[SCAL_OFF + SC_SH0 + (t - 66)] = acc;
            else if (t == 69)  sm[SCAL_OFF + SC_GAMMA] = 1.0f + softplusf(acc);
            else if (t < 134)  sm[ER_OFF + (t - 70)]  = sigf(acc);
            else               sm[AD_OFF + (t - 134)] = tanhf(acc);
        }
        __syncthreads();

        // ---- D2: key norm (warp 0) + shift softmax (thread 32) ----
        if (t < 32) {
            float k0 = sm[KEY_OFF + t], k1 = sm[KEY_OFF + t + 32];
            float sq = k0 * k0 + k1 * k1;
            #pragma unroll
            for (int o = 16; o; o >>= 1) sq += __shfl_down_sync(0xffffffffu, sq, o);
            if (t == 0) sm[SCAL_OFF + SC_KN] = fmaxf(sqrtf(sq), 1e-12f);
        } else if (t == 32) {
            float a0 = sm[SCAL_OFF + SC_SH0], a1 = sm[SCAL_OFF + SC_SH1], a2 = sm[SCAL_OFF + SC_SH2];
            float mx = fmaxf(a0, fmaxf(a1, a2));
            float e0 = expf(a0 - mx), e1 = expf(a1 - mx), e2 = expf(a2 - mx);
            float si = e0 + e1 + e2;
            sm[SCAL_OFF + SC_SH0] = e0 / si;
            sm[SCAL_OFF + SC_SH1] = e1 / si;
            sm[SCAL_OFF + SC_SH2] = e2 / si;
        }
        __syncthreads();

        // ---- E: content addressing + gate + shift + sharpen (replicated) ----
        {
            float beta  = sm[SCAL_OFF + SC_BETA];
            float gate  = sm[SCAL_OFF + SC_GATE];
            float gamma = sm[SCAL_OFF + SC_GAMMA];
            float kn    = sm[SCAL_OFF + SC_KN];
            float a = -INFINITY;
            if (t < NNM) {
                float dot = 0.0f, nrm = 0.0f;
                #pragma unroll 8
                for (int m = 0; m < MN; m++) {
                    float mv = sm[MEM_OFF + t * MEM_STR + m];
                    dot = fmaf(mv, sm[KEY_OFF + m], dot);
                    nrm = fmaf(mv, mv, nrm);
                }
                float sim = dot / (fmaxf(sqrtf(nrm), 1e-12f) * kn);
                a = beta * sim;
            }
            float amax = blockReduceMax(a, sm + RED_OFF);
            float e = (t < NNM) ? expf(a - amax) : 0.0f;
            float denom = blockReduceSum(e, sm + RED_OFF);
            if (t < NNM) {
                sm[WG_OFF + t] = gate * (e / denom) + (1.0f - gate) * sm[RW_OFF + t];
            }
            __syncthreads();
            float sh0 = sm[SCAL_OFF + SC_SH0];
            float sh1 = sm[SCAL_OFF + SC_SH1];
            float sh2 = sm[SCAL_OFF + SC_SH2];
            float ws = 0.0f;
            if (t < NNM) {
                float wv = sh0 * sm[WG_OFF + ((t + 1) & 255)]
                         + sh1 * sm[WG_OFF + t]
                         + sh2 * sm[WG_OFF + ((t + 255) & 255)];
                ws = powf(wv, gamma);
            }
            float wsum = blockReduceSum(ws, sm + RED_OFF);
            if (t < NNM) {
                float wn = ws / wsum;
                sm[WW_OFF + t] = wn;
                sm[RW_OFF + t] = wn;
            }
        }
        __syncthreads();

        // ---- F: rv = w @ mem (read BEFORE write), replicated ----
        {
            int m = t >> 3, rr = t & 7;
            float acc = 0.0f;
            for (int n = rr; n < NNM; n += 8)
                acc = fmaf(sm[WW_OFF + n], sm[MEM_OFF + n * MEM_STR + m], acc);
            #pragma unroll
            for (int o = 4; o; o >>= 1) acc += __shfl_down_sync(0xffffffffu, acc, o, 8);
            if (rr == 0) sm[HBc + 256 + m] = acc;
        }
        __syncthreads();

        // ---- store [h|rv] trace (rank 0 only, float4) ----
        if (r == 0 && t < KO4) g_hrv[((size_t)b * SN + s) * KO4 + t] =
            ((const float4*)(sm + HBc))[t];

        // ---- mem update (replicated) ----
        for (int i = t; i < NNM * MN; i += NT) {
            int n = i >> 6, m = i & 63;
            float wv = sm[WW_OFF + n];
            float* p = &sm[MEM_OFF + n * MEM_STR + m];
            *p = (*p) * (1.0f - wv * sm[ER_OFF + m]) + wv * sm[AD_OFF + m];
        }
        // next-iter phase A's barrier orders these writes before any reader
    }
}

// ================= deferred out-projection GEMM =================
#define OROWS 32
__global__ void __launch_bounds__(NT) ntm_out_kernel(
    const float* __restrict__ out_b, float* __restrict__ out)
{
    __shared__ float4 sh4[OROWS * KO4];   // 32 rows x 320 floats = 40KB
    const int t = threadIdx.x;
    const int r0 = blockIdx.x * OROWS;

    const float4* src = g_hrv + (size_t)r0 * KO4;
    #pragma unroll
    for (int i = t; i < OROWS * KO4; i += NT) sh4[i] = src[i];
    __syncthreads();

    float acc[OROWS];
    #pragma unroll
    for (int r = 0; r < OROWS; r++) acc[r] = 0.0f;

    #pragma unroll 2
    for (int kk = 0; kk < KO4; kk++) {
        float4 w = g_Wo[kk * VN + t];
        #pragma unroll
        for (int r = 0; r < OROWS; r++) {
            float4 hv = sh4[r * KO4 + kk];
            acc[r] = fmaf(w.x, hv.x, acc[r]);
            acc[r] = fmaf(w.y, hv.y, acc[r]);
            acc[r] = fmaf(w.z, hv.z, acc[r]);
            acc[r] = fmaf(w.w, hv.w, acc[r]);
        }
    }
    float bias = out_b[t];
    #pragma unroll
    for (int r = 0; r < OROWS; r++)
        out[(size_t)(r0 + r) * VN + t] = bias + acc[r];
}

extern "C" void kernel_launch(void* const* d_in, const int* in_sizes, int n_in,
                              void* d_out, int out_size) {
    const int*   x        = (const int*)  d_in[0];
    const float* emb      = (const float*)d_in[1];
    const float* W_ih     = (const float*)d_in[2];
    const float* W_hh     = (const float*)d_in[3];
    const float* b_ih     = (const float*)d_in[4];
    const float* b_hh     = (const float*)d_in[5];
    const float* key_W    = (const float*)d_in[6];
    const float* key_b    = (const float*)d_in[7];
    const float* beta_W   = (const float*)d_in[8];
    const float* beta_b   = (const float*)d_in[9];
    const float* gate_W   = (const float*)d_in[10];
    const float* gate_b   = (const float*)d_in[11];
    const float* shift_W  = (const float*)d_in[12];
    const float* shift_b  = (const float*)d_in[13];
    const float* gamma_W  = (const float*)d_in[14];
    const float* gamma_b  = (const float*)d_in[15];
    const float* erase_W  = (const float*)d_in[16];
    const float* erase_b  = (const float*)d_in[17];
    const float* add_W    = (const float*)d_in[18];
    const float* add_b    = (const float*)d_in[19];
    const float* out_W    = (const float*)d_in[20];
    const float* out_b    = (const float*)d_in[21];
    const float* mem_init = (const float*)d_in[22];
    float* out = (float*)d_out;

    int prep_blocks = (NP_TOTAL + 255) / 256;
    prep_kernel<<<prep_blocks, 256>>>(
        W_ih, W_hh, b_ih, b_hh,
        key_W, key_b, beta_W, beta_b, gate_W, gate_b,
        shift_W, shift_b, gamma_W, gamma_b,
        erase_W, erase_b, add_W, add_b, out_W);

    size_t smem_bytes = SMEM_FLOATS * sizeof(float);
    cudaFuncSetAttribute(ntm_kernel, cudaFuncAttributeMaxDynamicSharedMemorySize,
                         (int)smem_bytes);
    ntm_kernel<<<BN * 2, NT, smem_bytes>>>(x, emb, mem_init);

    ntm_out_kernel<<<(BN * SN) / OROWS, NT>>>(out_b, out);
}

// round 14
// speedup vs baseline: 1.6121x; 1.6121x over previous
#include <cuda_runtime.h>
#include <cuda_fp16.h>
#include <stdint.h>
#include <math.h>

// Problem constants
#define BN 64
#define SN 128
#define DN 128
#define VN 512
#define CN 256
#define NNM 256   // memory slots N
#define MN 64     // memory width M
#define NT 512    // threads per CTA

#define KG 448            // gates GEMV k (192 + 256)
#define KG8 (KG/8)        // 56
#define KH8 (CN/8)        // 32
#define KO 320            // out GEMV k (256 + 64)
#define KO4 (KO/4)        // 80
#define NHEAD 198

struct __align__(16) h8 { __half2 a, b, c, d; };   // 8 halves = 16B

// Weight panels (filled by prep kernel each launch)
__device__ h8     g_Wgh[KG8 * 1024];   // gates fp16: [g][row]
__device__ h8     g_Whh[KH8 * NHEAD];  // heads fp16: [g][row]
__device__ float4 g_Wo[KO4 * VN];      // out fp32:   [kk][row]
__device__ float  g_gb[1024];          // b_ih + b_hh
__device__ float  g_hb[NHEAD];         // head biases
// Recurrent trace: [h(256)|rv(64)] per (b,s) for the deferred out-projection
__device__ float4 g_hrv[BN * SN * KO4];

// ---------------- SMEM layout (float offsets) ----------------
#define MEM_OFF   0
#define MEM_STR   65
#define AV_OFF    16640   // [ci(192) | h(256) | rv(64)] = 512 floats
#define AV_CI     (AV_OFF)
#define AV_RVIN   (AV_OFF + 128)
#define AV_H      (AV_OFF + 192)
#define AV_RV     (AV_OFF + 448)
#define C_OFF     17152
#define G_OFF     17408
#define KEY_OFF   18432
#define ER_OFF    18496
#define AD_OFF    18560
#define RW_OFF    18624
#define WG_OFF    18880
#define WW_OFF    19136
#define RED_OFF   19392
#define SCAL_OFF  19412
#define XR_OFF    19420   // x row (128 ints)
#define SMEM_FLOATS 19552
// scal indices
#define SC_BETA 0
#define SC_GATE 1
#define SC_GAMMA 2
#define SC_SH0 3
#define SC_SH1 4
#define SC_SH2 5
#define SC_KN 6

__device__ __forceinline__ float sigf(float x) { return 1.0f / (1.0f + __expf(-x)); }
__device__ __forceinline__ float softplusf(float x) {
    return fmaxf(x, 0.0f) + log1pf(expf(-fabsf(x)));
}

__device__ __forceinline__ float blockReduceSum(float v, float* red) {
    #pragma unroll
    for (int o = 16; o; o >>= 1) v += __shfl_down_sync(0xffffffffu, v, o);
    int wid = threadIdx.x >> 5, lane = threadIdx.x & 31;
    __syncthreads();
    if (lane == 0) red[wid] = v;
    __syncthreads();
    if (wid == 0) {
        v = (lane < (NT / 32)) ? red[lane] : 0.0f;
        #pragma unroll
        for (int o = 8; o; o >>= 1) v += __shfl_down_sync(0xffffffffu, v, o);
        if (lane == 0) red[0] = v;
    }
    __syncthreads();
    return red[0];
}

// ================= prep: build weight panels =================
#define NP_WGH (KG8 * 1024)
#define NP_WHH (KH8 * NHEAD)
#define NP_WO  (KO4 * VN)
#define NP_GB  1024
#define NP_HB  NHEAD
#define NP_TOTAL (NP_WGH + NP_WHH + NP_WO + NP_GB + NP_HB)

__device__ __forceinline__ h8 pack8(float4 lo, float4 hi) {
    h8 r;
    r.a = __floats2half2_rn(lo.x, lo.y);
    r.b = __floats2half2_rn(lo.z, lo.w);
    r.c = __floats2half2_rn(hi.x, hi.y);
    r.d = __floats2half2_rn(hi.z, hi.w);
    return r;
}

__global__ void prep_kernel(
    const float* __restrict__ W_ih, const float* __restrict__ W_hh,
    const float* __restrict__ b_ih, const float* __restrict__ b_hh,
    const float* __restrict__ key_W, const float* __restrict__ key_b,
    const float* __restrict__ beta_W, const float* __restrict__ beta_b,
    const float* __restrict__ gate_W, const float* __restrict__ gate_b,
    const float* __restrict__ shift_W, const float* __restrict__ shift_b,
    const float* __restrict__ gamma_W, const float* __restrict__ gamma_b,
    const float* __restrict__ erase_W, const float* __restrict__ erase_b,
    const float* __restrict__ add_W, const float* __restrict__ add_b,
    const float* __restrict__ out_W)
{
    int idx = blockIdx.x * blockDim.x + threadIdx.x;
    if (idx < NP_WGH) {
        int g = idx >> 10, j = idx & 1023;
        int k = g * 8;
        float4 lo, hi;
        if (k < 192) {
            lo = *(const float4*)(W_ih + j * 192 + k);
            hi = *(const float4*)(W_ih + j * 192 + k + 4);
        } else {
            lo = *(const float4*)(W_hh + j * 256 + (k - 192));
            hi = *(const float4*)(W_hh + j * 256 + (k - 188));
        }
        g_Wgh[idx] = pack8(lo, hi);
        return;
    }
    idx -= NP_WGH;
    if (idx < NP_WHH) {
        int g = idx / NHEAD, j = idx % NHEAD;
        const float* wr;
        if (j < 64)        wr = key_W   + j * CN;
        else if (j == 64)  wr = beta_W;
        else if (j == 65)  wr = gate_W;
        else if (j < 69)   wr = shift_W + (j - 66) * CN;
        else if (j == 69)  wr = gamma_W;
        else if (j < 134)  wr = erase_W + (j - 70) * CN;
        else               wr = add_W   + (j - 134) * CN;
        int k = g * 8;
        float4 lo = *(const float4*)(wr + k);
        float4 hi = *(const float4*)(wr + k + 4);
        g_Whh[idx] = pack8(lo, hi);
        return;
    }
    idx -= NP_WHH;
    if (idx < NP_WO) {
        int kk = idx >> 9, j = idx & 511;
        g_Wo[idx] = *(const float4*)(out_W + j * KO + kk * 4);
        return;
    }
    idx -= NP_WO;
    if (idx < NP_GB) { g_gb[idx] = b_ih[idx] + b_hh[idx]; return; }
    idx -= NP_GB;
    if (idx < NP_HB) {
        int j = idx;
        float bias;
        if (j < 64)        bias = key_b[j];
        else if (j == 64)  bias = beta_b[0];
        else if (j == 65)  bias = gate_b[0];
        else if (j < 69)   bias = shift_b[j - 66];
        else if (j == 69)  bias = gamma_b[0];
        else if (j < 134)  bias = erase_b[j - 70];
        else               bias = add_b[j - 134];
        g_hb[j] = bias;
    }
}

// ================= main persistent kernel: 1 CTA per batch =================
extern __shared__ float sm[];

__global__ void __launch_bounds__(NT, 1) ntm_kernel(
    const int*   __restrict__ x,
    const float* __restrict__ emb,
    const float* __restrict__ mem_init)
{
    const int t = threadIdx.x;
    const int b = blockIdx.x;

    // ---- init state ----
    for (int i = t; i < NNM * MN; i += NT) {
        int n = i >> 6, m = i & 63;
        sm[MEM_OFF + n * MEM_STR + m] = mem_init[(b * NNM + n) * MN + m];
    }
    for (int i = t; i < 512; i += NT) sm[AV_OFF + i] = 0.0f;
    for (int i = t; i < CN; i += NT) sm[C_OFF + i] = 0.0f;
    for (int i = t; i < NNM; i += NT) sm[RW_OFF + i] = 0.0f;
    if (t < SN) ((int*)sm)[XR_OFF + t] = x[b * SN + t];
    __syncthreads();

    const float gb0 = g_gb[t];
    const float gb1 = g_gb[t + 512];
    float hbr = 0.0f;
    if (t < NHEAD) hbr = g_hb[t];

    for (int s = 0; s < SN; s++) {
        // ---- A: build ci = [emb[x], rv_prev] ----
        if (t < MN) {
            sm[AV_RVIN + t] = sm[AV_RV + t];
        } else if (t >= 64 && t < 64 + DN) {
            int tt = t - 64;
            int xi = ((int*)sm)[XR_OFF + s];
            sm[AV_CI + tt] = emb[xi * DN + tt];
        }
        __syncthreads();

        // ---- B: gates GEMV (fp16 weights), 16 LDG.128 in flight per thread ----
        {
            const float4* av4 = (const float4*)(sm + AV_OFF);
            float4 a0 = make_float4(0.f, 0.f, 0.f, 0.f);
            float4 a1 = make_float4(0.f, 0.f, 0.f, 0.f);
            #pragma unroll 1
            for (int kb = 0; kb < KG8; kb += 8) {
                const h8* p = &g_Wgh[kb * 1024 + t];
                h8 w0[8], w1[8];
                #pragma unroll
                for (int u = 0; u < 8; u++) { w0[u] = p[u * 1024]; w1[u] = p[u * 1024 + 512]; }
                #pragma unroll
                for (int u = 0; u < 8; u++) {
                    float4 av0 = av4[(kb + u) * 2];
                    float4 av1 = av4[(kb + u) * 2 + 1];
                    float2 f;
                    f = __half22float2(w0[u].a); a0.x = fmaf(f.x, av0.x, a0.x); a0.y = fmaf(f.y, av0.y, a0.y);
                    f = __half22float2(w0[u].b); a0.z = fmaf(f.x, av0.z, a0.z); a0.w = fmaf(f.y, av0.w, a0.w);
                    f = __half22float2(w0[u].c); a0.x = fmaf(f.x, av1.x, a0.x); a0.y = fmaf(f.y, av1.y, a0.y);
                    f = __half22float2(w0[u].d); a0.z = fmaf(f.x, av1.z, a0.z); a0.w = fmaf(f.y, av1.w, a0.w);
                    f = __half22float2(w1[u].a); a1.x = fmaf(f.x, av0.x, a1.x); a1.y = fmaf(f.y, av0.y, a1.y);
                    f = __half22float2(w1[u].b); a1.z = fmaf(f.x, av0.z, a1.z); a1.w = fmaf(f.y, av0.w, a1.w);
                    f = __half22float2(w1[u].c); a1.x = fmaf(f.x, av1.x, a1.x); a1.y = fmaf(f.y, av1.y, a1.y);
                    f = __half22float2(w1[u].d); a1.z = fmaf(f.x, av1.z, a1.z); a1.w = fmaf(f.y, av1.w, a1.w);
                }
            }
            sm[G_OFF + t]       = gb0 + (a0.x + a0.y) + (a0.z + a0.w);
            sm[G_OFF + 512 + t] = gb1 + (a1.x + a1.y) + (a1.z + a1.w);
        }
        __syncthreads();

        // ---- C: LSTM pointwise (torch order i,f,g,o) ----
        if (t < CN) {
            float ig = sm[G_OFF + t];
            float fg = sm[G_OFF + CN + t];
            float gg = sm[G_OFF + 2 * CN + t];
            float og = sm[G_OFF + 3 * CN + t];
            float cc = sigf(fg) * sm[C_OFF + t] + sigf(ig) * tanhf(gg);
            sm[C_OFF + t] = cc;
            sm[AV_H + t] = sigf(og) * tanhf(cc);
        }
        __syncthreads();

        // ---- D: head projections (198 rows x 256), 8 LDG in flight ----
        if (t < NHEAD) {
            const float4* h4 = (const float4*)(sm + AV_H);
            float4 a = make_float4(0.f, 0.f, 0.f, 0.f);
            #pragma unroll 1
            for (int kb = 0; kb < KH8; kb += 8) {
                const h8* p = &g_Whh[kb * NHEAD + t];
                h8 w[8];
                #pragma unroll
                for (int u = 0; u < 8; u++) w[u] = p[u * NHEAD];
                #pragma unroll
                for (int u = 0; u < 8; u++) {
                    float4 hv0 = h4[(kb + u) * 2];
                    float4 hv1 = h4[(kb + u) * 2 + 1];
                    float2 f;
                    f = __half22float2(w[u].a); a.x = fmaf(f.x, hv0.x, a.x); a.y = fmaf(f.y, hv0.y, a.y);
                    f = __half22float2(w[u].b); a.z = fmaf(f.x, hv0.z, a.z); a.w = fmaf(f.y, hv0.w, a.w);
                    f = __half22float2(w[u].c); a.x = fmaf(f.x, hv1.x, a.x); a.y = fmaf(f.y, hv1.y, a.y);
                    f = __half22float2(w[u].d); a.z = fmaf(f.x, hv1.z, a.z); a.w = fmaf(f.y, hv1.w, a.w);
                }
            }
            float acc = hbr + (a.x + a.y) + (a.z + a.w);
            if (t < 64)        sm[KEY_OFF + t] = acc;
            else if (t == 64)  sm[SCAL_OFF + SC_BETA]  = softplusf(acc);
            else if (t == 65)  sm[SCAL_OFF + SC_GATE]  = sigf(acc);
            else if (t < 69)   sm[SCAL_OFF + SC_SH0 + (t - 66)] = acc;
            else if (t == 69)  sm[SCAL_OFF + SC_GAMMA] = 1.0f + softplusf(acc);
            else if (t < 134)  sm[ER_OFF + (t - 70)]  = sigf(acc);
            else               sm[AD_OFF + (t - 134)] = tanhf(acc);
        }
        __syncthreads();

        // ---- D2: key norm (warp 0) + shift softmax (thread 32) ----
        if (t < 32) {
            float k0 = sm[KEY_OFF + t], k1 = sm[KEY_OFF + t + 32];
            float sq = k0 * k0 + k1 * k1;
            #pragma unroll
            for (int o = 16; o; o >>= 1) sq += __shfl_down_sync(0xffffffffu, sq, o);
            if (t == 0) sm[SCAL_OFF + SC_KN] = fmaxf(sqrtf(sq), 1e-12f);
        } else if (t == 32) {
            float a0 = sm[SCAL_OFF + SC_SH0], a1 = sm[SCAL_OFF + SC_SH1], a2 = sm[SCAL_OFF + SC_SH2];
            float mx = fmaxf(a0, fmaxf(a1, a2));
            float e0 = expf(a0 - mx), e1 = expf(a1 - mx), e2 = expf(a2 - mx);
            float si = e0 + e1 + e2;
            sm[SCAL_OFF + SC_SH0] = e0 / si;
            sm[SCAL_OFF + SC_SH1] = e1 / si;
            sm[SCAL_OFF + SC_SH2] = e2 / si;
        }
        __syncthreads();

        // ---- E: content addressing + gate + shift + sharpen ----
        // Softmax WITHOUT max-subtraction: a = beta*sim, |a| <= beta (O(1)),
        // far from exp overflow; result identical up to fp rounding.
        {
            float beta  = sm[SCAL_OFF + SC_BETA];
            float gate  = sm[SCAL_OFF + SC_GATE];
            float gamma = sm[SCAL_OFF + SC_GAMMA];
            float kn    = sm[SCAL_OFF + SC_KN];
            float e = 0.0f;
            if (t < NNM) {
                float dot = 0.0f, nrm = 0.0f;
                #pragma unroll 8
                for (int m = 0; m < MN; m++) {
                    float mv = sm[MEM_OFF + t * MEM_STR + m];
                    dot = fmaf(mv, sm[KEY_OFF + m], dot);
                    nrm = fmaf(mv, mv, nrm);
                }
                float sim = dot / (fmaxf(sqrtf(nrm), 1e-12f) * kn);
                e = __expf(beta * sim);
            }
            float denom = blockReduceSum(e, sm + RED_OFF);
            if (t < NNM) {
                sm[WG_OFF + t] = gate * (e / denom) + (1.0f - gate) * sm[RW_OFF + t];
            }
            __syncthreads();
            float sh0 = sm[SCAL_OFF + SC_SH0];
            float sh1 = sm[SCAL_OFF + SC_SH1];
            float sh2 = sm[SCAL_OFF + SC_SH2];
            float ws = 0.0f;
            if (t < NNM) {
                float wv = sh0 * sm[WG_OFF + ((t + 1) & 255)]
                         + sh1 * sm[WG_OFF + t]
                         + sh2 * sm[WG_OFF + ((t + 255) & 255)];
                ws = __powf(wv, gamma);
            }
            float wsum = blockReduceSum(ws, sm + RED_OFF);
            if (t < NNM) {
                float wn = ws / wsum;
                sm[WW_OFF + t] = wn;
                sm[RW_OFF + t] = wn;
            }
        }
        __syncthreads();

        // ---- F: rv = w @ mem (read BEFORE write) ----
        {
            int m = t >> 3, r = t & 7;
            float acc = 0.0f;
            for (int n = r; n < NNM; n += 8)
                acc = fmaf(sm[WW_OFF + n], sm[MEM_OFF + n * MEM_STR + m], acc);
            #pragma unroll
            for (int o = 4; o; o >>= 1) acc += __shfl_down_sync(0xffffffffu, acc, o, 8);
            if (r == 0) sm[AV_RV + m] = acc;
        }
        __syncthreads();

        // ---- store [h|rv] trace for deferred out-projection (float4) ----
        if (t < KO4) g_hrv[((size_t)b * SN + s) * KO4 + t] =
            ((const float4*)(sm + AV_H))[t];

        // ---- mem update ----
        for (int i = t; i < NNM * MN; i += NT) {
            int n = i >> 6, m = i & 63;
            float wv = sm[WW_OFF + n];
            float* p = &sm[MEM_OFF + n * MEM_STR + m];
            *p = (*p) * (1.0f - wv * sm[ER_OFF + m]) + wv * sm[AD_OFF + m];
        }
        // next-iter phase A's barrier orders mem/hrv writes before later readers
    }
}

// ================= deferred out-projection GEMM =================
#define OROWS 32
__global__ void __launch_bounds__(NT) ntm_out_kernel(
    const float* __restrict__ out_b, float* __restrict__ out)
{
    __shared__ float4 sh4[OROWS * KO4];   // 32 rows x 320 floats = 40KB
    const int t = threadIdx.x;
    const int r0 = blockIdx.x * OROWS;

    const float4* src = g_hrv + (size_t)r0 * KO4;
    #pragma unroll
    for (int i = t; i < OROWS * KO4; i += NT) sh4[i] = src[i];
    __syncthreads();

    float acc[OROWS];
    #pragma unroll
    for (int r = 0; r < OROWS; r++) acc[r] = 0.0f;

    #pragma unroll 2
    for (int kk = 0; kk < KO4; kk++) {
        float4 w = g_Wo[kk * VN + t];
        #pragma unroll
        for (int r = 0; r < OROWS; r++) {
            float4 hv = sh4[r * KO4 + kk];
            acc[r] = fmaf(w.x, hv.x, acc[r]);
            acc[r] = fmaf(w.y, hv.y, acc[r]);
            acc[r] = fmaf(w.z, hv.z, acc[r]);
            acc[r] = fmaf(w.w, hv.w, acc[r]);
        }
    }
    float bias = out_b[t];
    #pragma unroll
    for (int r = 0; r < OROWS; r++)
        out[(size_t)(r0 + r) * VN + t] = bias + acc[r];
}

extern "C" void kernel_launch(void* const* d_in, const int* in_sizes, int n_in,
                              void* d_out, int out_size) {
    const int*   x        = (const int*)  d_in[0];
    const float* emb      = (const float*)d_in[1];
    const float* W_ih     = (const float*)d_in[2];
    const float* W_hh     = (const float*)d_in[3];
    const float* b_ih     = (const float*)d_in[4];
    const float* b_hh     = (const float*)d_in[5];
    const float* key_W    = (const float*)d_in[6];
    const float* key_b    = (const float*)d_in[7];
    const float* beta_W   = (const float*)d_in[8];
    const float* beta_b   = (const float*)d_in[9];
    const float* gate_W   = (const float*)d_in[10];
    const float* gate_b   = (const float*)d_in[11];
    const float* shift_W  = (const float*)d_in[12];
    const float* shift_b  = (const float*)d_in[13];
    const float* gamma_W  = (const float*)d_in[14];
    const float* gamma_b  = (const float*)d_in[15];
    const float* erase_W  = (const float*)d_in[16];
    const float* erase_b  = (const float*)d_in[17];
    const float* add_W    = (const float*)d_in[18];
    const float* add_b    = (const float*)d_in[19];
    const float* out_W    = (const float*)d_in[20];
    const float* out_b    = (const float*)d_in[21];
    const float* mem_init = (const float*)d_in[22];
    float* out = (float*)d_out;

    int prep_blocks = (NP_TOTAL + 255) / 256;
    prep_kernel<<<prep_blocks, 256>>>(
        W_ih, W_hh, b_ih, b_hh,
        key_W, key_b, beta_W, beta_b, gate_W, gate_b,
        shift_W, shift_b, gamma_W, gamma_b,
        erase_W, erase_b, add_W, add_b, out_W);

    size_t smem_bytes = SMEM_FLOATS * sizeof(float);
    cudaFuncSetAttribute(ntm_kernel, cudaFuncAttributeMaxDynamicSharedMemorySize,
                         (int)smem_bytes);
    ntm_kernel<<<BN, NT, smem_bytes>>>(x, emb, mem_init);

    ntm_out_kernel<<<(BN * SN) / OROWS, NT>>>(out_b, out);
}